// round 1
// baseline (speedup 1.0000x reference)
#include <cuda_runtime.h>
#include <math.h>

#define NH   16
#define DH   64
#define DM   1024
#define BB   2
#define LQ   2048
#define LK   2048
#define MTOT (BB*LQ)        // 4096

// Head-major projected scratch: [(b*NH+h), L, DH]
__device__ float g_Qh[BB*NH*LQ*DH];
__device__ float g_Kh[BB*NH*LK*DH];
__device__ float g_Vh[BB*NH*LK*DH];

// ---------------------------------------------------------------------------
// Projection: C[m,n] = sum_k A[m,k]*W[n,k] + bias[n], written head-major.
// M=4096, N=1024, K=1024. Tiles 64x64, K-step 16, 256 threads, 4x4 micro.
// blockIdx.z selects (q,Wq,bq)->Qh, (k,Wk,bk)->Kh, (v,Wv,bv)->Vh.
// ---------------------------------------------------------------------------
__global__ __launch_bounds__(256) void proj_kernel(
    const float* __restrict__ q, const float* __restrict__ k, const float* __restrict__ v,
    const float* __restrict__ Wq, const float* __restrict__ bq,
    const float* __restrict__ Wk, const float* __restrict__ bk,
    const float* __restrict__ Wv, const float* __restrict__ bv)
{
    const float *A, *W, *bias;
    float* out;
    if (blockIdx.z == 0)      { A = q; W = Wq; bias = bq; out = g_Qh; }
    else if (blockIdx.z == 1) { A = k; W = Wk; bias = bk; out = g_Kh; }
    else                      { A = v; W = Wv; bias = bv; out = g_Vh; }

    __shared__ float As[16][68];
    __shared__ float Ws[16][68];

    const int tid = threadIdx.x;
    const int tx = tid & 15, ty = tid >> 4;
    const int m0 = blockIdx.y * 64;
    const int n0 = blockIdx.x * 64;

    float acc[4][4];
#pragma unroll
    for (int i = 0; i < 4; i++)
#pragma unroll
        for (int j = 0; j < 4; j++) acc[i][j] = 0.f;

    const int lrow = tid >> 2;       // 0..63
    const int lq   = tid & 3;        // 0..3 (quad of 4 floats)

    for (int k0 = 0; k0 < DM; k0 += 16) {
        float4 av = *(const float4*)(A + (size_t)(m0 + lrow) * DM + k0 + lq * 4);
        As[lq*4+0][lrow] = av.x; As[lq*4+1][lrow] = av.y;
        As[lq*4+2][lrow] = av.z; As[lq*4+3][lrow] = av.w;
        float4 wv = *(const float4*)(W + (size_t)(n0 + lrow) * DM + k0 + lq * 4);
        Ws[lq*4+0][lrow] = wv.x; Ws[lq*4+1][lrow] = wv.y;
        Ws[lq*4+2][lrow] = wv.z; Ws[lq*4+3][lrow] = wv.w;
        __syncthreads();
#pragma unroll
        for (int kk = 0; kk < 16; kk++) {
            float4 a = *(float4*)&As[kk][ty * 4];
            float4 w = *(float4*)&Ws[kk][tx * 4];
            acc[0][0] += a.x*w.x; acc[0][1] += a.x*w.y; acc[0][2] += a.x*w.z; acc[0][3] += a.x*w.w;
            acc[1][0] += a.y*w.x; acc[1][1] += a.y*w.y; acc[1][2] += a.y*w.z; acc[1][3] += a.y*w.w;
            acc[2][0] += a.z*w.x; acc[2][1] += a.z*w.y; acc[2][2] += a.z*w.z; acc[2][3] += a.z*w.w;
            acc[3][0] += a.w*w.x; acc[3][1] += a.w*w.y; acc[3][2] += a.w*w.z; acc[3][3] += a.w*w.w;
        }
        __syncthreads();
    }

    // Epilogue: n0 is a multiple of 64 -> whole block maps to one head.
    const int h = n0 >> 6;
    const float4 bv4 = *(const float4*)(bias + n0 + tx * 4);
#pragma unroll
    for (int i = 0; i < 4; i++) {
        int m = m0 + ty * 4 + i;
        int b = m >> 11;            // /LQ
        int r = m & (LQ - 1);
        float4 o = make_float4(acc[i][0] + bv4.x, acc[i][1] + bv4.y,
                               acc[i][2] + bv4.z, acc[i][3] + bv4.w);
        *(float4*)(out + (((size_t)b * NH + h) * LQ + r) * DH + tx * 4) = o;
    }
}

// ---------------------------------------------------------------------------
// Fused masked attention with dual output (P@K and P@V), online softmax.
// Grid: (LQ/64, B*NH). 256 threads (16x16), 4x4 microtiles.
// ---------------------------------------------------------------------------
#define SM_QTS 0            // [d][r] 64x64
#define SM_KTS 4096         // [d][c] 64x64
#define SM_KS  8192         // [c][d] 64x64
#define SM_VS  12288        // [c][d] 64x64
#define SM_PS  16384        // [r][c] 64x68
#define SM_FLOATS (16384 + 64*68)

__global__ __launch_bounds__(256, 2) void attn_kernel(
    const int* __restrict__ mask, float* __restrict__ out_k, float* __restrict__ out_v)
{
    extern __shared__ float sm[];
    float* Qts = sm + SM_QTS;
    float* Kts = sm + SM_KTS;
    float* Ks  = sm + SM_KS;
    float* Vs  = sm + SM_VS;
    float* Ps  = sm + SM_PS;

    const int tid = threadIdx.x;
    const int tx = tid & 15, ty = tid >> 4;
    const int q0 = blockIdx.x * 64;
    const int by = blockIdx.y;          // b*NH + h
    const int b  = by >> 4;
    const int h  = by & 15;

    const float* Qg = g_Qh + ((size_t)by * LQ + q0) * DH;
    const float* Kg = g_Kh + (size_t)by * LK * DH;
    const float* Vg = g_Vh + (size_t)by * LK * DH;

    // Load Q tile once, transposed [d][r], with 1/8 scale folded in.
#pragma unroll
    for (int rep = 0; rep < 4; rep++) {
        int f4 = tid + 256 * rep;       // 0..1023 float4 slots
        int r  = f4 >> 4;
        int qd = f4 & 15;
        float4 qv = *(const float4*)(Qg + (size_t)r * DH + qd * 4);
        Qts[(qd*4+0)*64 + r] = qv.x * 0.125f;
        Qts[(qd*4+1)*64 + r] = qv.y * 0.125f;
        Qts[(qd*4+2)*64 + r] = qv.z * 0.125f;
        Qts[(qd*4+3)*64 + r] = qv.w * 0.125f;
    }

    float mi[4], li[4], ov[4][4], ok[4][4];
#pragma unroll
    for (int i = 0; i < 4; i++) {
        mi[i] = -1e30f; li[i] = 0.f;
#pragma unroll
        for (int j = 0; j < 4; j++) { ov[i][j] = 0.f; ok[i][j] = 0.f; }
    }

    for (int k0 = 0; k0 < LK; k0 += 64) {
        __syncthreads();   // previous GEMM done reading Ks/Vs/Ps (and Q store visible)
        // Load K (dual layout) and V tiles
#pragma unroll
        for (int rep = 0; rep < 4; rep++) {
            int f4 = tid + 256 * rep;
            int c  = f4 >> 4;
            int qd = f4 & 15;
            float4 kv = *(const float4*)(Kg + (size_t)(k0 + c) * DH + qd * 4);
            *(float4*)&Ks[c * 64 + qd * 4] = kv;
            Kts[(qd*4+0)*64 + c] = kv.x;
            Kts[(qd*4+1)*64 + c] = kv.y;
            Kts[(qd*4+2)*64 + c] = kv.z;
            Kts[(qd*4+3)*64 + c] = kv.w;
            float4 vv = *(const float4*)(Vg + (size_t)(k0 + c) * DH + qd * 4);
            *(float4*)&Vs[c * 64 + qd * 4] = vv;
        }
        __syncthreads();

        // S = (Q/8) K^T : 4x4 microtile per thread
        float s[4][4];
#pragma unroll
        for (int i = 0; i < 4; i++)
#pragma unroll
            for (int j = 0; j < 4; j++) s[i][j] = 0.f;
#pragma unroll 8
        for (int d = 0; d < DH; d++) {
            float4 a = *(float4*)&Qts[d * 64 + ty * 4];
            float4 kk = *(float4*)&Kts[d * 64 + tx * 4];
            s[0][0] += a.x*kk.x; s[0][1] += a.x*kk.y; s[0][2] += a.x*kk.z; s[0][3] += a.x*kk.w;
            s[1][0] += a.y*kk.x; s[1][1] += a.y*kk.y; s[1][2] += a.y*kk.z; s[1][3] += a.y*kk.w;
            s[2][0] += a.z*kk.x; s[2][1] += a.z*kk.y; s[2][2] += a.z*kk.z; s[2][3] += a.z*kk.w;
            s[3][0] += a.w*kk.x; s[3][1] += a.w*kk.y; s[3][2] += a.w*kk.z; s[3][3] += a.w*kk.w;
        }

        // Mask + online softmax update
#pragma unroll
        for (int i = 0; i < 4; i++) {
            int r = q0 + ty * 4 + i;
            int4 mm = *(const int4*)(mask + ((size_t)b * LQ + r) * LK + k0 + tx * 4);
            if (mm.x == 0) s[i][0] = -1e30f;
            if (mm.y == 0) s[i][1] = -1e30f;
            if (mm.z == 0) s[i][2] = -1e30f;
            if (mm.w == 0) s[i][3] = -1e30f;

            float mx = fmaxf(fmaxf(s[i][0], s[i][1]), fmaxf(s[i][2], s[i][3]));
#pragma unroll
            for (int off = 8; off > 0; off >>= 1)
                mx = fmaxf(mx, __shfl_xor_sync(0xffffffffu, mx, off, 16));
            float mnew = fmaxf(mi[i], mx);
            float alpha = __expf(mi[i] - mnew);
            float rs = 0.f;
#pragma unroll
            for (int j = 0; j < 4; j++) {
                float p = __expf(s[i][j] - mnew);
                s[i][j] = p;
                rs += p;
            }
#pragma unroll
            for (int off = 8; off > 0; off >>= 1)
                rs += __shfl_xor_sync(0xffffffffu, rs, off, 16);
            li[i] = li[i] * alpha + rs;
            mi[i] = mnew;
#pragma unroll
            for (int j = 0; j < 4; j++) { ov[i][j] *= alpha; ok[i][j] *= alpha; }
            // stash P
            *(float4*)&Ps[(ty * 4 + i) * 68 + tx * 4] = make_float4(s[i][0], s[i][1], s[i][2], s[i][3]);
        }
        __syncthreads();

        // O_v += P V ; O_k += P K
#pragma unroll 4
        for (int c = 0; c < 64; c++) {
            float p0 = Ps[(ty*4+0)*68 + c];
            float p1 = Ps[(ty*4+1)*68 + c];
            float p2 = Ps[(ty*4+2)*68 + c];
            float p3 = Ps[(ty*4+3)*68 + c];
            float4 vv = *(float4*)&Vs[c * 64 + tx * 4];
            float4 kv = *(float4*)&Ks[c * 64 + tx * 4];
            ov[0][0] += p0*vv.x; ov[0][1] += p0*vv.y; ov[0][2] += p0*vv.z; ov[0][3] += p0*vv.w;
            ov[1][0] += p1*vv.x; ov[1][1] += p1*vv.y; ov[1][2] += p1*vv.z; ov[1][3] += p1*vv.w;
            ov[2][0] += p2*vv.x; ov[2][1] += p2*vv.y; ov[2][2] += p2*vv.z; ov[2][3] += p2*vv.w;
            ov[3][0] += p3*vv.x; ov[3][1] += p3*vv.y; ov[3][2] += p3*vv.z; ov[3][3] += p3*vv.w;
            ok[0][0] += p0*kv.x; ok[0][1] += p0*kv.y; ok[0][2] += p0*kv.z; ok[0][3] += p0*kv.w;
            ok[1][0] += p1*kv.x; ok[1][1] += p1*kv.y; ok[1][2] += p1*kv.z; ok[1][3] += p1*kv.w;
            ok[2][0] += p2*kv.x; ok[2][1] += p2*kv.y; ok[2][2] += p2*kv.z; ok[2][3] += p2*kv.w;
            ok[3][0] += p3*kv.x; ok[3][1] += p3*kv.y; ok[3][2] += p3*kv.z; ok[3][3] += p3*kv.w;
        }
    }

    // Normalize + store. Output layout: [b, l, h*DH + d]
#pragma unroll
    for (int i = 0; i < 4; i++) {
        float inv = 1.f / li[i];
        int r = q0 + ty * 4 + i;
        size_t o = ((size_t)b * LQ + r) * DM + h * DH + tx * 4;
        *(float4*)(out_k + o) = make_float4(ok[i][0]*inv, ok[i][1]*inv, ok[i][2]*inv, ok[i][3]*inv);
        *(float4*)(out_v + o) = make_float4(ov[i][0]*inv, ov[i][1]*inv, ov[i][2]*inv, ov[i][3]*inv);
    }
}

// ---------------------------------------------------------------------------
extern "C" void kernel_launch(void* const* d_in, const int* in_sizes, int n_in,
                              void* d_out, int out_size)
{
    // metadata order (setup_inputs dict): q,k,v,mask,Wq,bq,Wk,bk,Wv,bv
    const float* q    = (const float*)d_in[0];
    const float* k    = (const float*)d_in[1];
    const float* v    = (const float*)d_in[2];
    const int*   mask = (const int*)  d_in[3];
    const float* Wq   = (const float*)d_in[4];
    const float* bq   = (const float*)d_in[5];
    const float* Wk   = (const float*)d_in[6];
    const float* bk   = (const float*)d_in[7];
    const float* Wv   = (const float*)d_in[8];
    const float* bv   = (const float*)d_in[9];

    float* out_k = (float*)d_out;                       // first tuple element
    float* out_v = (float*)d_out + (size_t)BB * LQ * DM; // second tuple element

    static int smem_set = 0;
    if (!smem_set) {
        cudaFuncSetAttribute(attn_kernel, cudaFuncAttributeMaxDynamicSharedMemorySize,
                             SM_FLOATS * (int)sizeof(float));
        smem_set = 1;
    }

    dim3 pgrid(DM / 64, MTOT / 64, 3);
    proj_kernel<<<pgrid, 256>>>(q, k, v, Wq, bq, Wk, bk, Wv, bv);

    dim3 agrid(LQ / 64, BB * NH);
    attn_kernel<<<agrid, 256, SM_FLOATS * (int)sizeof(float)>>>(mask, out_k, out_v);
}

// round 4
// speedup vs baseline: 1.9783x; 1.9783x over previous
#include <cuda_runtime.h>
#include <math.h>

#define NH   16
#define DH   64
#define DM   1024
#define BB   2
#define LQ   2048
#define LK   2048
#define MTOT (BB*LQ)        // 4096

// Head-major projected scratch: [(b*NH+h), L, DH]
__device__ float g_Qh[BB*NH*LQ*DH];
__device__ float g_Kh[BB*NH*LK*DH];
__device__ float g_Vh[BB*NH*LK*DH];

__device__ __forceinline__ unsigned f2tf(float f) {
    unsigned r;
    asm("cvt.rna.tf32.f32 %0, %1;" : "=r"(r) : "f"(f));
    return r;
}

__device__ __forceinline__ void mma_tf32(float* d, const unsigned* a, const unsigned* b) {
    asm volatile(
        "mma.sync.aligned.m16n8k8.row.col.f32.tf32.tf32.f32 "
        "{%0,%1,%2,%3}, {%4,%5,%6,%7}, {%8,%9}, {%0,%1,%2,%3};"
        : "+f"(d[0]), "+f"(d[1]), "+f"(d[2]), "+f"(d[3])
        : "r"(a[0]), "r"(a[1]), "r"(a[2]), "r"(a[3]), "r"(b[0]), "r"(b[1]));
}

// ---------------------------------------------------------------------------
// Projection: C[m,n] = sum_k A[m,k]*W[n,k] + bias[n], head-major out.
// M=4096, N=1024, K=1024. BM=128, BN=128, BK=32, 256 threads, tf32 MMA.
// ---------------------------------------------------------------------------
#define PST 36   // smem row stride (words)

__global__ __launch_bounds__(256) void proj_kernel(
    const float* __restrict__ q, const float* __restrict__ k, const float* __restrict__ v,
    const float* __restrict__ Wq, const float* __restrict__ bq,
    const float* __restrict__ Wk, const float* __restrict__ bk,
    const float* __restrict__ Wv, const float* __restrict__ bv)
{
    const float *A, *W, *bias;
    float* out;
    if (blockIdx.z == 0)      { A = q; W = Wq; bias = bq; out = g_Qh; }
    else if (blockIdx.z == 1) { A = k; W = Wk; bias = bk; out = g_Kh; }
    else                      { A = v; W = Wv; bias = bv; out = g_Vh; }

    __shared__ unsigned As[128 * PST];
    __shared__ unsigned Ws[128 * PST];

    const int tid  = threadIdx.x;
    const int warp = tid >> 5, lane = tid & 31;
    const int g = lane >> 2, tg = lane & 3;
    const int wm = warp >> 2;       // 0..1 : 64 rows each
    const int wn = warp & 3;        // 0..3 : 32 cols each
    const int m0 = blockIdx.y * 128;
    const int n0 = blockIdx.x * 128;

    float acc[4][4][4];
#pragma unroll
    for (int mt = 0; mt < 4; mt++)
#pragma unroll
        for (int nt = 0; nt < 4; nt++)
#pragma unroll
            for (int i = 0; i < 4; i++) acc[mt][nt][i] = 0.f;

    const int lrow = tid >> 3;      // 0..31 pairs with rep
    const int lc4  = tid & 7;       // float4 slot in 32-wide row

    for (int k0 = 0; k0 < DM; k0 += 32) {
        __syncthreads();
#pragma unroll
        for (int rep = 0; rep < 4; rep++) {
            int row = lrow + rep * 32;
            float4 av = *(const float4*)(A + (size_t)(m0 + row) * DM + k0 + lc4 * 4);
            *(uint4*)&As[row * PST + lc4 * 4] =
                make_uint4(f2tf(av.x), f2tf(av.y), f2tf(av.z), f2tf(av.w));
            float4 wv = *(const float4*)(W + (size_t)(n0 + row) * DM + k0 + lc4 * 4);
            *(uint4*)&Ws[row * PST + lc4 * 4] =
                make_uint4(f2tf(wv.x), f2tf(wv.y), f2tf(wv.z), f2tf(wv.w));
        }
        __syncthreads();

#pragma unroll
        for (int kk = 0; kk < 4; kk++) {
            unsigned a[4][4], b[4][2];
#pragma unroll
            for (int mt = 0; mt < 4; mt++) {
                int base = (wm * 64 + mt * 16 + g) * PST + kk * 8 + tg;
                a[mt][0] = As[base];
                a[mt][1] = As[base + 8 * PST];
                a[mt][2] = As[base + 4];
                a[mt][3] = As[base + 8 * PST + 4];
            }
#pragma unroll
            for (int nt = 0; nt < 4; nt++) {
                int base = (wn * 32 + nt * 8 + g) * PST + kk * 8 + tg;
                b[nt][0] = Ws[base];
                b[nt][1] = Ws[base + 4];
            }
#pragma unroll
            for (int mt = 0; mt < 4; mt++)
#pragma unroll
                for (int nt = 0; nt < 4; nt++)
                    mma_tf32(acc[mt][nt], a[mt], b[nt]);
        }
    }

    // Epilogue: head-major store with bias.
#pragma unroll
    for (int nt = 0; nt < 4; nt++) {
        int n = n0 + wn * 32 + nt * 8 + 2 * tg;
        int h = n >> 6, d = n & 63;
        float2 bb = *(const float2*)(bias + n);
#pragma unroll
        for (int mt = 0; mt < 4; mt++) {
            int m = m0 + wm * 64 + mt * 16 + g;
            int b_ = m >> 11, r = m & (LQ - 1);
            float* p0 = out + (((size_t)b_ * NH + h) * LQ + r) * DH + d;
            *(float2*)p0 = make_float2(acc[mt][nt][0] + bb.x, acc[mt][nt][1] + bb.y);
            float* p1 = out + (((size_t)b_ * NH + h) * LQ + (r + 8)) * DH + d;
            *(float2*)p1 = make_float2(acc[mt][nt][2] + bb.x, acc[mt][nt][3] + bb.y);
        }
    }
}

// ---------------------------------------------------------------------------
// Fused attention, tf32 MMA. BLOCK_Q=128, BK=64, 8 warps; each warp owns 16
// full rows -> warp-local softmax. Dual output P@V and P@K.
// ---------------------------------------------------------------------------
#define SKN 68   // Kn row stride (key-major, [key][d])
#define SKT 65   // Kt/Vt row stride (d-major, [d][key])
#define SPP 68   // P / Q-stage row stride ([row][col])

#define KN_OFF 0
#define KT_OFF (64 * SKN)
#define VT_OFF (KT_OFF + 64 * SKT)
#define PP_OFF (VT_OFF + 64 * SKT)
#define SM_WORDS (PP_OFF + 128 * SPP)

__global__ __launch_bounds__(256, 1) void attn_kernel(
    const int* __restrict__ mask, float* __restrict__ out_k, float* __restrict__ out_v)
{
    extern __shared__ unsigned sm[];
    unsigned* Kn = sm + KN_OFF;
    unsigned* Kt = sm + KT_OFF;
    unsigned* Vt = sm + VT_OFF;
    unsigned* Pp = sm + PP_OFF;

    const int tid  = threadIdx.x;
    const int warp = tid >> 5, lane = tid & 31;
    const int g = lane >> 2, tg = lane & 3;
    const int q0 = blockIdx.x * 128;
    const int by = blockIdx.y;           // b*NH + h
    const int b  = by >> 4;
    const int h  = by & 15;
    const int w16 = warp * 16;

    const float* Qg = g_Qh + ((size_t)by * LQ + q0) * DH;
    const float* Kg = g_Kh + (size_t)by * LK * DH;
    const float* Vg = g_Vh + (size_t)by * LK * DH;

    // ---- Stage Q (scaled) into Pp, then pull per-warp A-fragments ----
#pragma unroll
    for (int rep = 0; rep < 8; rep++) {
        int idx = tid + 256 * rep;       // 2048 float4 slots
        int r = idx >> 4, d4 = idx & 15;
        float4 qv = *(const float4*)(Qg + (size_t)r * DH + d4 * 4);
        *(uint4*)&Pp[r * SPP + d4 * 4] = make_uint4(
            __float_as_uint(qv.x * 0.125f), __float_as_uint(qv.y * 0.125f),
            __float_as_uint(qv.z * 0.125f), __float_as_uint(qv.w * 0.125f));
    }
    __syncthreads();

    unsigned qf[8][4];
#pragma unroll
    for (int kb = 0; kb < 8; kb++) {
        int base = (w16 + g) * SPP + kb * 8 + tg;
        qf[kb][0] = f2tf(__uint_as_float(Pp[base]));
        qf[kb][1] = f2tf(__uint_as_float(Pp[base + 8 * SPP]));
        qf[kb][2] = f2tf(__uint_as_float(Pp[base + 4]));
        qf[kb][3] = f2tf(__uint_as_float(Pp[base + 8 * SPP + 4]));
    }

    float mi0 = -1e30f, mi1 = -1e30f, li0 = 0.f, li1 = 0.f;
    float ov[8][4], ok[8][4];
#pragma unroll
    for (int nt = 0; nt < 8; nt++)
#pragma unroll
        for (int i = 0; i < 4; i++) { ov[nt][i] = 0.f; ok[nt][i] = 0.f; }

    // K/V load mapping: per warp, keys c = warp*8 + (lane>>2), d = 16*rep + 4*(lane&3)
    const int ldc = warp * 8 + g;
    const int ldd = tg * 4;

    for (int k0 = 0; k0 < LK; k0 += 64) {
        __syncthreads();
#pragma unroll
        for (int rep = 0; rep < 4; rep++) {
            int d = 16 * rep + ldd;
            float4 kv = *(const float4*)(Kg + (size_t)(k0 + ldc) * DH + d);
            unsigned t0 = f2tf(kv.x), t1 = f2tf(kv.y), t2 = f2tf(kv.z), t3 = f2tf(kv.w);
            Kn[ldc * SKN + d]     = t0; Kn[ldc * SKN + d + 1] = t1;
            Kn[ldc * SKN + d + 2] = t2; Kn[ldc * SKN + d + 3] = t3;
            Kt[(d    ) * SKT + ldc] = t0; Kt[(d + 1) * SKT + ldc] = t1;
            Kt[(d + 2) * SKT + ldc] = t2; Kt[(d + 3) * SKT + ldc] = t3;
            float4 vv = *(const float4*)(Vg + (size_t)(k0 + ldc) * DH + d);
            Vt[(d    ) * SKT + ldc] = f2tf(vv.x); Vt[(d + 1) * SKT + ldc] = f2tf(vv.y);
            Vt[(d + 2) * SKT + ldc] = f2tf(vv.z); Vt[(d + 3) * SKT + ldc] = f2tf(vv.w);
        }
        __syncthreads();

        // ---- S = Q K^T : 16 x 64 per warp ----
        float s[8][4];
#pragma unroll
        for (int nt = 0; nt < 8; nt++)
#pragma unroll
            for (int i = 0; i < 4; i++) s[nt][i] = 0.f;
#pragma unroll
        for (int kb = 0; kb < 8; kb++) {
#pragma unroll
            for (int nt = 0; nt < 8; nt++) {
                unsigned bfr[2];
                int base = (nt * 8 + g) * SKN + kb * 8 + tg;
                bfr[0] = Kn[base]; bfr[1] = Kn[base + 4];
                mma_tf32(s[nt], qf[kb], bfr);
            }
        }

        // ---- mask + online softmax (warp-local) ----
        const int qr0 = q0 + w16 + g;
        const size_t mrow0 = ((size_t)b * LQ + qr0) * LK + k0;
        const size_t mrow1 = mrow0 + 8 * (size_t)LK;
#pragma unroll
        for (int nt = 0; nt < 8; nt++) {
            int col = nt * 8 + 2 * tg;
            int2 m0v = *(const int2*)(mask + mrow0 + col);
            int2 m1v = *(const int2*)(mask + mrow1 + col);
            if (m0v.x == 0) s[nt][0] = -1e30f;
            if (m0v.y == 0) s[nt][1] = -1e30f;
            if (m1v.x == 0) s[nt][2] = -1e30f;
            if (m1v.y == 0) s[nt][3] = -1e30f;
        }
        float mx0 = -1e30f, mx1 = -1e30f;
#pragma unroll
        for (int nt = 0; nt < 8; nt++) {
            mx0 = fmaxf(mx0, fmaxf(s[nt][0], s[nt][1]));
            mx1 = fmaxf(mx1, fmaxf(s[nt][2], s[nt][3]));
        }
        mx0 = fmaxf(mx0, __shfl_xor_sync(0xffffffffu, mx0, 1));
        mx0 = fmaxf(mx0, __shfl_xor_sync(0xffffffffu, mx0, 2));
        mx1 = fmaxf(mx1, __shfl_xor_sync(0xffffffffu, mx1, 1));
        mx1 = fmaxf(mx1, __shfl_xor_sync(0xffffffffu, mx1, 2));
        float mn0 = fmaxf(mi0, mx0), mn1 = fmaxf(mi1, mx1);
        float al0 = __expf(mi0 - mn0), al1 = __expf(mi1 - mn1);
        float rs0 = 0.f, rs1 = 0.f;
#pragma unroll
        for (int nt = 0; nt < 8; nt++) {
            s[nt][0] = __expf(s[nt][0] - mn0); rs0 += s[nt][0];
            s[nt][1] = __expf(s[nt][1] - mn0); rs0 += s[nt][1];
            s[nt][2] = __expf(s[nt][2] - mn1); rs1 += s[nt][2];
            s[nt][3] = __expf(s[nt][3] - mn1); rs1 += s[nt][3];
        }
        rs0 += __shfl_xor_sync(0xffffffffu, rs0, 1);
        rs0 += __shfl_xor_sync(0xffffffffu, rs0, 2);
        rs1 += __shfl_xor_sync(0xffffffffu, rs1, 1);
        rs1 += __shfl_xor_sync(0xffffffffu, rs1, 2);
        li0 = li0 * al0 + rs0; li1 = li1 * al1 + rs1;
        mi0 = mn0; mi1 = mn1;
#pragma unroll
        for (int nt = 0; nt < 8; nt++) {
            ov[nt][0] *= al0; ov[nt][1] *= al0; ov[nt][2] *= al1; ov[nt][3] *= al1;
            ok[nt][0] *= al0; ok[nt][1] *= al0; ok[nt][2] *= al1; ok[nt][3] *= al1;
        }

        // ---- stash P as tf32 (warp-private rows) ----
#pragma unroll
        for (int nt = 0; nt < 8; nt++) {
            int base = (w16 + g) * SPP + nt * 8 + 2 * tg;
            Pp[base]               = f2tf(s[nt][0]);
            Pp[base + 1]           = f2tf(s[nt][1]);
            Pp[base + 8 * SPP]     = f2tf(s[nt][2]);
            Pp[base + 8 * SPP + 1] = f2tf(s[nt][3]);
        }
        __syncwarp();

        // ---- O_v += P V ; O_k += P K ----
#pragma unroll
        for (int kb = 0; kb < 8; kb++) {
            unsigned pa[4];
            int base = (w16 + g) * SPP + kb * 8 + tg;
            pa[0] = Pp[base];
            pa[1] = Pp[base + 8 * SPP];
            pa[2] = Pp[base + 4];
            pa[3] = Pp[base + 8 * SPP + 4];
#pragma unroll
            for (int nt = 0; nt < 8; nt++) {
                unsigned vb[2], kb2[2];
                int bb2 = (nt * 8 + g) * SKT + kb * 8 + tg;
                vb[0] = Vt[bb2]; vb[1] = Vt[bb2 + 4];
                mma_tf32(ov[nt], pa, vb);
                kb2[0] = Kt[bb2]; kb2[1] = Kt[bb2 + 4];
                mma_tf32(ok[nt], pa, kb2);
            }
        }
    }

    // ---- normalize + store: out[b, l, h*64 + d] ----
    float inv0 = 1.f / li0, inv1 = 1.f / li1;
    int r0 = q0 + w16 + g;
#pragma unroll
    for (int nt = 0; nt < 8; nt++) {
        int d = nt * 8 + 2 * tg;
        size_t o0 = ((size_t)b * LQ + r0) * DM + h * DH + d;
        size_t o1 = ((size_t)b * LQ + r0 + 8) * DM + h * DH + d;
        *(float2*)(out_v + o0) = make_float2(ov[nt][0] * inv0, ov[nt][1] * inv0);
        *(float2*)(out_v + o1) = make_float2(ov[nt][2] * inv1, ov[nt][3] * inv1);
        *(float2*)(out_k + o0) = make_float2(ok[nt][0] * inv0, ok[nt][1] * inv0);
        *(float2*)(out_k + o1) = make_float2(ok[nt][2] * inv1, ok[nt][3] * inv1);
    }
}

// ---------------------------------------------------------------------------
extern "C" void kernel_launch(void* const* d_in, const int* in_sizes, int n_in,
                              void* d_out, int out_size)
{
    const float* q    = (const float*)d_in[0];
    const float* k    = (const float*)d_in[1];
    const float* v    = (const float*)d_in[2];
    const int*   mask = (const int*)  d_in[3];
    const float* Wq   = (const float*)d_in[4];
    const float* bq   = (const float*)d_in[5];
    const float* Wk   = (const float*)d_in[6];
    const float* bk   = (const float*)d_in[7];
    const float* Wv   = (const float*)d_in[8];
    const float* bv   = (const float*)d_in[9];

    float* out_k = (float*)d_out;
    float* out_v = (float*)d_out + (size_t)BB * LQ * DM;

    static int smem_set = 0;
    if (!smem_set) {
        cudaFuncSetAttribute(attn_kernel, cudaFuncAttributeMaxDynamicSharedMemorySize,
                             SM_WORDS * (int)sizeof(unsigned));
        smem_set = 1;
    }

    dim3 pgrid(DM / 128, MTOT / 128, 3);
    proj_kernel<<<pgrid, 256>>>(q, k, v, Wq, bq, Wk, bk, Wv, bv);

    dim3 agrid(LQ / 128, BB * NH);
    attn_kernel<<<agrid, 256, SM_WORDS * (int)sizeof(unsigned)>>>(mask, out_k, out_v);
}

// round 9
// speedup vs baseline: 2.0483x; 1.0354x over previous
#include <cuda_runtime.h>
#include <math.h>

#define NH   16
#define DH   64
#define DM   1024
#define BB   2
#define LQ   2048
#define LK   2048
#define MTOT (BB*LQ)

// Head-major projected scratch: [(b*NH+h), L, DH]
__device__ float g_Qh[BB*NH*LQ*DH];
__device__ float g_Kh[BB*NH*LK*DH];
__device__ float g_Vh[BB*NH*LK*DH];

__device__ __forceinline__ unsigned f2tf(float f) {
    unsigned r;
    asm("cvt.rna.tf32.f32 %0, %1;" : "=r"(r) : "f"(f));
    return r;
}

__device__ __forceinline__ void mma_tf32(float* d, const unsigned* a, const unsigned* b) {
    asm volatile(
        "mma.sync.aligned.m16n8k8.row.col.f32.tf32.tf32.f32 "
        "{%0,%1,%2,%3}, {%4,%5,%6,%7}, {%8,%9}, {%0,%1,%2,%3};"
        : "+f"(d[0]), "+f"(d[1]), "+f"(d[2]), "+f"(d[3])
        : "r"(a[0]), "r"(a[1]), "r"(a[2]), "r"(a[3]), "r"(b[0]), "r"(b[1]));
}

// ---------------------------------------------------------------------------
// Projection (unchanged, verified): warp-mma tf32, head-major out.
// ---------------------------------------------------------------------------
#define PST 36

__global__ __launch_bounds__(256) void proj_kernel(
    const float* __restrict__ q, const float* __restrict__ k, const float* __restrict__ v,
    const float* __restrict__ Wq, const float* __restrict__ bq,
    const float* __restrict__ Wk, const float* __restrict__ bk,
    const float* __restrict__ Wv, const float* __restrict__ bv)
{
    const float *A, *W, *bias;
    float* out;
    if (blockIdx.z == 0)      { A = q; W = Wq; bias = bq; out = g_Qh; }
    else if (blockIdx.z == 1) { A = k; W = Wk; bias = bk; out = g_Kh; }
    else                      { A = v; W = Wv; bias = bv; out = g_Vh; }

    __shared__ unsigned As[128 * PST];
    __shared__ unsigned Ws[128 * PST];

    const int tid  = threadIdx.x;
    const int warp = tid >> 5, lane = tid & 31;
    const int g = lane >> 2, tg = lane & 3;
    const int wm = warp >> 2;
    const int wn = warp & 3;
    const int m0 = blockIdx.y * 128;
    const int n0 = blockIdx.x * 128;

    float acc[4][4][4];
#pragma unroll
    for (int mt = 0; mt < 4; mt++)
#pragma unroll
        for (int nt = 0; nt < 4; nt++)
#pragma unroll
            for (int i = 0; i < 4; i++) acc[mt][nt][i] = 0.f;

    const int lrow = tid >> 3;
    const int lc4  = tid & 7;

    for (int k0 = 0; k0 < DM; k0 += 32) {
        __syncthreads();
#pragma unroll
        for (int rep = 0; rep < 4; rep++) {
            int row = lrow + rep * 32;
            float4 av = *(const float4*)(A + (size_t)(m0 + row) * DM + k0 + lc4 * 4);
            *(uint4*)&As[row * PST + lc4 * 4] =
                make_uint4(f2tf(av.x), f2tf(av.y), f2tf(av.z), f2tf(av.w));
            float4 wv = *(const float4*)(W + (size_t)(n0 + row) * DM + k0 + lc4 * 4);
            *(uint4*)&Ws[row * PST + lc4 * 4] =
                make_uint4(f2tf(wv.x), f2tf(wv.y), f2tf(wv.z), f2tf(wv.w));
        }
        __syncthreads();

#pragma unroll
        for (int kk = 0; kk < 4; kk++) {
            unsigned a[4][4], b[4][2];
#pragma unroll
            for (int mt = 0; mt < 4; mt++) {
                int base = (wm * 64 + mt * 16 + g) * PST + kk * 8 + tg;
                a[mt][0] = As[base];
                a[mt][1] = As[base + 8 * PST];
                a[mt][2] = As[base + 4];
                a[mt][3] = As[base + 8 * PST + 4];
            }
#pragma unroll
            for (int nt = 0; nt < 4; nt++) {
                int base = (wn * 32 + nt * 8 + g) * PST + kk * 8 + tg;
                b[nt][0] = Ws[base];
                b[nt][1] = Ws[base + 4];
            }
#pragma unroll
            for (int mt = 0; mt < 4; mt++)
#pragma unroll
                for (int nt = 0; nt < 4; nt++)
                    mma_tf32(acc[mt][nt], a[mt], b[nt]);
        }
    }

#pragma unroll
    for (int nt = 0; nt < 4; nt++) {
        int n = n0 + wn * 32 + nt * 8 + 2 * tg;
        int h = n >> 6, d = n & 63;
        float2 bb = *(const float2*)(bias + n);
#pragma unroll
        for (int mt = 0; mt < 4; mt++) {
            int m = m0 + wm * 64 + mt * 16 + g;
            int b_ = m >> 11, r = m & (LQ - 1);
            float* p0 = out + (((size_t)b_ * NH + h) * LQ + r) * DH + d;
            *(float2*)p0 = make_float2(acc[mt][nt][0] + bb.x, acc[mt][nt][1] + bb.y);
            float* p1 = out + (((size_t)b_ * NH + h) * LQ + (r + 8)) * DH + d;
            *(float2*)p1 = make_float2(acc[mt][nt][2] + bb.x, acc[mt][nt][3] + bb.y);
        }
    }
}

// ---------------------------------------------------------------------------
// Fused attention, warp-role split. 512 threads.
// Warps 0-7:  S = Q K^T, softmax, P -> smem, O_v += P V   (rows wr*16..+15)
// Warps 8-15: O_k += P K (same rows; alpha/linv via smem)
// ---------------------------------------------------------------------------
#define SKN 68   // Kn row stride ([key][d])
#define SKT 65   // Kt/Vt row stride ([d][key])
#define SPP 68   // P / Q row stride ([row][col])

#define KN_OFF 0
#define KT_OFF (64 * SKN)
#define VT_OFF (KT_OFF + 64 * SKT)
#define PP_OFF (VT_OFF + 64 * SKT)
#define QS_OFF (PP_OFF + 128 * SPP)
#define AL_OFF (QS_OFF + 128 * SPP)
#define LI_OFF (AL_OFF + 128)
#define SM_WORDS (LI_OFF + 128)

__global__ __launch_bounds__(512, 1) void attn_kernel(
    const int* __restrict__ mask, float* __restrict__ out_k, float* __restrict__ out_v)
{
    extern __shared__ unsigned sm[];
    unsigned* Kn = sm + KN_OFF;
    unsigned* Kt = sm + KT_OFF;
    unsigned* Vt = sm + VT_OFF;
    unsigned* Pp = sm + PP_OFF;
    unsigned* Qs = sm + QS_OFF;
    float* alphas = (float*)(sm + AL_OFF);
    float* linv   = (float*)(sm + LI_OFF);

    const int tid  = threadIdx.x;
    const int warp = tid >> 5, lane = tid & 31;
    const int g = lane >> 2, tg = lane & 3;
    const int role = warp >> 3;          // 0: S/softmax/O_v   1: O_k
    const int wr   = warp & 7;           // row-group (16 rows each)
    const int w16  = wr * 16;
    const int q0 = blockIdx.x * 128;
    const int by = blockIdx.y;           // b*NH + h
    const int b  = by >> 4;
    const int h  = by & 15;

    const float* Qg = g_Qh + ((size_t)by * LQ + q0) * DH;
    const float* Kg = g_Kh + (size_t)by * LK * DH;
    const float* Vg = g_Vh + (size_t)by * LK * DH;

    // ---- Stage Q (scaled, tf32) into Qs ----
#pragma unroll
    for (int rep = 0; rep < 4; rep++) {
        int idx = tid + 512 * rep;       // 2048 float4 slots
        int r = idx >> 4, d4 = idx & 15;
        float4 qv = *(const float4*)(Qg + (size_t)r * DH + d4 * 4);
        *(uint4*)&Qs[r * SPP + d4 * 4] = make_uint4(
            f2tf(qv.x * 0.125f), f2tf(qv.y * 0.125f),
            f2tf(qv.z * 0.125f), f2tf(qv.w * 0.125f));
    }

    float mi0 = -1e30f, mi1 = -1e30f, li0 = 0.f, li1 = 0.f;
    float oacc[8][4];                    // role0: O_v, role1: O_k
#pragma unroll
    for (int nt = 0; nt < 8; nt++)
#pragma unroll
        for (int i = 0; i < 4; i++) oacc[nt][i] = 0.f;

    for (int k0 = 0; k0 < LK; k0 += 64) {
        __syncthreads();   // prior O-phase done reading Kn/Kt/Vt/Pp

        // ---- all 16 warps: load K (dual layout) + V tiles ----
#pragma unroll
        for (int rep = 0; rep < 2; rep++) {
            int idx = tid + 512 * rep;   // 1024 float4 slots
            int key = idx >> 4, c4 = idx & 15;
            int d = c4 * 4;
            float4 kv = *(const float4*)(Kg + (size_t)(k0 + key) * DH + d);
            unsigned t0 = f2tf(kv.x), t1 = f2tf(kv.y), t2 = f2tf(kv.z), t3 = f2tf(kv.w);
            Kn[key * SKN + d]     = t0; Kn[key * SKN + d + 1] = t1;
            Kn[key * SKN + d + 2] = t2; Kn[key * SKN + d + 3] = t3;
            Kt[(d    ) * SKT + key] = t0; Kt[(d + 1) * SKT + key] = t1;
            Kt[(d + 2) * SKT + key] = t2; Kt[(d + 3) * SKT + key] = t3;
            float4 vv = *(const float4*)(Vg + (size_t)(k0 + key) * DH + d);
            Vt[(d    ) * SKT + key] = f2tf(vv.x); Vt[(d + 1) * SKT + key] = f2tf(vv.y);
            Vt[(d + 2) * SKT + key] = f2tf(vv.z); Vt[(d + 3) * SKT + key] = f2tf(vv.w);
        }
        __syncthreads();

        if (role == 0) {
            // ---- S = Q K^T : 16 x 64 ----
            float s[8][4];
#pragma unroll
            for (int nt = 0; nt < 8; nt++)
#pragma unroll
                for (int i = 0; i < 4; i++) s[nt][i] = 0.f;
#pragma unroll
            for (int kb = 0; kb < 8; kb++) {
                unsigned qa[4];
                int qb = (w16 + g) * SPP + kb * 8 + tg;
                qa[0] = Qs[qb];
                qa[1] = Qs[qb + 8 * SPP];
                qa[2] = Qs[qb + 4];
                qa[3] = Qs[qb + 8 * SPP + 4];
#pragma unroll
                for (int nt = 0; nt < 8; nt++) {
                    unsigned bfr[2];
                    int base = (nt * 8 + g) * SKN + kb * 8 + tg;
                    bfr[0] = Kn[base]; bfr[1] = Kn[base + 4];
                    mma_tf32(s[nt], qa, bfr);
                }
            }

            // ---- mask + online softmax (warp-local) ----
            const int qr0 = q0 + w16 + g;
            const size_t mrow0 = ((size_t)b * LQ + qr0) * LK + k0;
            const size_t mrow1 = mrow0 + 8 * (size_t)LK;
#pragma unroll
            for (int nt = 0; nt < 8; nt++) {
                int col = nt * 8 + 2 * tg;
                int2 m0v = *(const int2*)(mask + mrow0 + col);
                int2 m1v = *(const int2*)(mask + mrow1 + col);
                if (m0v.x == 0) s[nt][0] = -1e30f;
                if (m0v.y == 0) s[nt][1] = -1e30f;
                if (m1v.x == 0) s[nt][2] = -1e30f;
                if (m1v.y == 0) s[nt][3] = -1e30f;
            }
            float mx0 = -1e30f, mx1 = -1e30f;
#pragma unroll
            for (int nt = 0; nt < 8; nt++) {
                mx0 = fmaxf(mx0, fmaxf(s[nt][0], s[nt][1]));
                mx1 = fmaxf(mx1, fmaxf(s[nt][2], s[nt][3]));
            }
            mx0 = fmaxf(mx0, __shfl_xor_sync(0xffffffffu, mx0, 1));
            mx0 = fmaxf(mx0, __shfl_xor_sync(0xffffffffu, mx0, 2));
            mx1 = fmaxf(mx1, __shfl_xor_sync(0xffffffffu, mx1, 1));
            mx1 = fmaxf(mx1, __shfl_xor_sync(0xffffffffu, mx1, 2));
            float mn0 = fmaxf(mi0, mx0), mn1 = fmaxf(mi1, mx1);
            float al0 = __expf(mi0 - mn0), al1 = __expf(mi1 - mn1);
            float rs0 = 0.f, rs1 = 0.f;
#pragma unroll
            for (int nt = 0; nt < 8; nt++) {
                s[nt][0] = __expf(s[nt][0] - mn0); rs0 += s[nt][0];
                s[nt][1] = __expf(s[nt][1] - mn0); rs0 += s[nt][1];
                s[nt][2] = __expf(s[nt][2] - mn1); rs1 += s[nt][2];
                s[nt][3] = __expf(s[nt][3] - mn1); rs1 += s[nt][3];
            }
            rs0 += __shfl_xor_sync(0xffffffffu, rs0, 1);
            rs0 += __shfl_xor_sync(0xffffffffu, rs0, 2);
            rs1 += __shfl_xor_sync(0xffffffffu, rs1, 1);
            rs1 += __shfl_xor_sync(0xffffffffu, rs1, 2);
            li0 = li0 * al0 + rs0; li1 = li1 * al1 + rs1;
            mi0 = mn0; mi1 = mn1;
#pragma unroll
            for (int nt = 0; nt < 8; nt++) {
                oacc[nt][0] *= al0; oacc[nt][1] *= al0;
                oacc[nt][2] *= al1; oacc[nt][3] *= al1;
            }
            // stash P (tf32) + alphas
#pragma unroll
            for (int nt = 0; nt < 8; nt++) {
                int base = (w16 + g) * SPP + nt * 8 + 2 * tg;
                Pp[base]               = f2tf(s[nt][0]);
                Pp[base + 1]           = f2tf(s[nt][1]);
                Pp[base + 8 * SPP]     = f2tf(s[nt][2]);
                Pp[base + 8 * SPP + 1] = f2tf(s[nt][3]);
            }
            if (tg == 0) {
                alphas[w16 + g]     = al0;
                alphas[w16 + 8 + g] = al1;
            }
        }
        __syncthreads();   // P + alphas visible

        // ---- O-phase ----
        if (role == 0) {
#pragma unroll
            for (int kb = 0; kb < 8; kb++) {
                unsigned pa[4];
                int base = (w16 + g) * SPP + kb * 8 + tg;
                pa[0] = Pp[base];
                pa[1] = Pp[base + 8 * SPP];
                pa[2] = Pp[base + 4];
                pa[3] = Pp[base + 8 * SPP + 4];
#pragma unroll
                for (int nt = 0; nt < 8; nt++) {
                    unsigned vb[2];
                    int bb2 = (nt * 8 + g) * SKT + kb * 8 + tg;
                    vb[0] = Vt[bb2]; vb[1] = Vt[bb2 + 4];
                    mma_tf32(oacc[nt], pa, vb);
                }
            }
        } else {
            float a0 = alphas[w16 + g], a1 = alphas[w16 + 8 + g];
#pragma unroll
            for (int nt = 0; nt < 8; nt++) {
                oacc[nt][0] *= a0; oacc[nt][1] *= a0;
                oacc[nt][2] *= a1; oacc[nt][3] *= a1;
            }
#pragma unroll
            for (int kb = 0; kb < 8; kb++) {
                unsigned pa[4];
                int base = (w16 + g) * SPP + kb * 8 + tg;
                pa[0] = Pp[base];
                pa[1] = Pp[base + 8 * SPP];
                pa[2] = Pp[base + 4];
                pa[3] = Pp[base + 8 * SPP + 4];
#pragma unroll
                for (int nt = 0; nt < 8; nt++) {
                    unsigned kb2[2];
                    int bb2 = (nt * 8 + g) * SKT + kb * 8 + tg;
                    kb2[0] = Kt[bb2]; kb2[1] = Kt[bb2 + 4];
                    mma_tf32(oacc[nt], pa, kb2);
                }
            }
        }
    }

    // ---- epilogue ----
    float inv0, inv1;
    if (role == 0) {
        inv0 = 1.f / li0; inv1 = 1.f / li1;
        if (tg == 0) {
            linv[w16 + g]     = inv0;
            linv[w16 + 8 + g] = inv1;
        }
    }
    __syncthreads();
    if (role == 1) {
        inv0 = linv[w16 + g];
        inv1 = linv[w16 + 8 + g];
    }
    float* outp = (role == 0) ? out_v : out_k;
    int r0 = q0 + w16 + g;
#pragma unroll
    for (int nt = 0; nt < 8; nt++) {
        int d = nt * 8 + 2 * tg;
        size_t o0 = ((size_t)b * LQ + r0) * DM + h * DH + d;
        size_t o1 = ((size_t)b * LQ + r0 + 8) * DM + h * DH + d;
        *(float2*)(outp + o0) = make_float2(oacc[nt][0] * inv0, oacc[nt][1] * inv0);
        *(float2*)(outp + o1) = make_float2(oacc[nt][2] * inv1, oacc[nt][3] * inv1);
    }
}

// ---------------------------------------------------------------------------
extern "C" void kernel_launch(void* const* d_in, const int* in_sizes, int n_in,
                              void* d_out, int out_size)
{
    const float* q    = (const float*)d_in[0];
    const float* k    = (const float*)d_in[1];
    const float* v    = (const float*)d_in[2];
    const int*   mask = (const int*)  d_in[3];
    const float* Wq   = (const float*)d_in[4];
    const float* bq   = (const float*)d_in[5];
    const float* Wk   = (const float*)d_in[6];
    const float* bk   = (const float*)d_in[7];
    const float* Wv   = (const float*)d_in[8];
    const float* bv   = (const float*)d_in[9];

    float* out_k = (float*)d_out;
    float* out_v = (float*)d_out + (size_t)BB * LQ * DM;

    static int smem_set = 0;
    if (!smem_set) {
        cudaFuncSetAttribute(attn_kernel, cudaFuncAttributeMaxDynamicSharedMemorySize,
                             SM_WORDS * (int)sizeof(unsigned));
        smem_set = 1;
    }

    dim3 pgrid(DM / 128, MTOT / 128, 3);
    proj_kernel<<<pgrid, 256>>>(q, k, v, Wq, bq, Wk, bk, Wv, bv);

    dim3 agrid(LQ / 128, BB * NH);
    attn_kernel<<<agrid, 512, SM_WORDS * (int)sizeof(unsigned)>>>(mask, out_k, out_v);
}

// round 10
// speedup vs baseline: 3.0056x; 1.4673x over previous
#include <cuda_runtime.h>
#include <math.h>

#define NH   16
#define DH   64
#define DM   1024
#define BB   2
#define LQ   2048
#define LK   2048
#define MTOT (BB*LQ)
#define NT   (LK/64)

// Head-major projected scratch: [(b*NH+h), L, DH]
__device__ float g_Qh[BB*NH*LQ*DH];
__device__ float g_Kh[BB*NH*LK*DH];
__device__ float g_Vh[BB*NH*LK*DH];

__device__ __forceinline__ unsigned f2tf(float f) {
    unsigned r;
    asm("cvt.rna.tf32.f32 %0, %1;" : "=r"(r) : "f"(f));
    return r;
}

__device__ __forceinline__ void mma_tf32(float* d, const unsigned* a, const unsigned* b) {
    asm volatile(
        "mma.sync.aligned.m16n8k8.row.col.f32.tf32.tf32.f32 "
        "{%0,%1,%2,%3}, {%4,%5,%6,%7}, {%8,%9}, {%0,%1,%2,%3};"
        : "+f"(d[0]), "+f"(d[1]), "+f"(d[2]), "+f"(d[3])
        : "r"(a[0]), "r"(a[1]), "r"(a[2]), "r"(a[3]), "r"(b[0]), "r"(b[1]));
}

// ---------------------------------------------------------------------------
// Projection (unchanged, verified): warp-mma tf32, head-major out.
// ---------------------------------------------------------------------------
#define PST 36

__global__ __launch_bounds__(256) void proj_kernel(
    const float* __restrict__ q, const float* __restrict__ k, const float* __restrict__ v,
    const float* __restrict__ Wq, const float* __restrict__ bq,
    const float* __restrict__ Wk, const float* __restrict__ bk,
    const float* __restrict__ Wv, const float* __restrict__ bv)
{
    const float *A, *W, *bias;
    float* out;
    if (blockIdx.z == 0)      { A = q; W = Wq; bias = bq; out = g_Qh; }
    else if (blockIdx.z == 1) { A = k; W = Wk; bias = bk; out = g_Kh; }
    else                      { A = v; W = Wv; bias = bv; out = g_Vh; }

    __shared__ unsigned As[128 * PST];
    __shared__ unsigned Ws[128 * PST];

    const int tid  = threadIdx.x;
    const int warp = tid >> 5, lane = tid & 31;
    const int g = lane >> 2, tg = lane & 3;
    const int wm = warp >> 2;
    const int wn = warp & 3;
    const int m0 = blockIdx.y * 128;
    const int n0 = blockIdx.x * 128;

    float acc[4][4][4];
#pragma unroll
    for (int mt = 0; mt < 4; mt++)
#pragma unroll
        for (int nt = 0; nt < 4; nt++)
#pragma unroll
            for (int i = 0; i < 4; i++) acc[mt][nt][i] = 0.f;

    const int lrow = tid >> 3;
    const int lc4  = tid & 7;

    for (int k0 = 0; k0 < DM; k0 += 32) {
        __syncthreads();
#pragma unroll
        for (int rep = 0; rep < 4; rep++) {
            int row = lrow + rep * 32;
            float4 av = *(const float4*)(A + (size_t)(m0 + row) * DM + k0 + lc4 * 4);
            *(uint4*)&As[row * PST + lc4 * 4] =
                make_uint4(f2tf(av.x), f2tf(av.y), f2tf(av.z), f2tf(av.w));
            float4 wv = *(const float4*)(W + (size_t)(n0 + row) * DM + k0 + lc4 * 4);
            *(uint4*)&Ws[row * PST + lc4 * 4] =
                make_uint4(f2tf(wv.x), f2tf(wv.y), f2tf(wv.z), f2tf(wv.w));
        }
        __syncthreads();

#pragma unroll
        for (int kk = 0; kk < 4; kk++) {
            unsigned a[4][4], b[4][2];
#pragma unroll
            for (int mt = 0; mt < 4; mt++) {
                int base = (wm * 64 + mt * 16 + g) * PST + kk * 8 + tg;
                a[mt][0] = As[base];
                a[mt][1] = As[base + 8 * PST];
                a[mt][2] = As[base + 4];
                a[mt][3] = As[base + 8 * PST + 4];
            }
#pragma unroll
            for (int nt = 0; nt < 4; nt++) {
                int base = (wn * 32 + nt * 8 + g) * PST + kk * 8 + tg;
                b[nt][0] = Ws[base];
                b[nt][1] = Ws[base + 4];
            }
#pragma unroll
            for (int mt = 0; mt < 4; mt++)
#pragma unroll
                for (int nt = 0; nt < 4; nt++)
                    mma_tf32(acc[mt][nt], a[mt], b[nt]);
        }
    }

#pragma unroll
    for (int nt = 0; nt < 4; nt++) {
        int n = n0 + wn * 32 + nt * 8 + 2 * tg;
        int h = n >> 6, d = n & 63;
        float2 bb = *(const float2*)(bias + n);
#pragma unroll
        for (int mt = 0; mt < 4; mt++) {
            int m = m0 + wm * 64 + mt * 16 + g;
            int b_ = m >> 11, r = m & (LQ - 1);
            float* p0 = out + (((size_t)b_ * NH + h) * LQ + r) * DH + d;
            *(float2*)p0 = make_float2(acc[mt][nt][0] + bb.x, acc[mt][nt][1] + bb.y);
            float* p1 = out + (((size_t)b_ * NH + h) * LQ + (r + 8)) * DH + d;
            *(float2*)p1 = make_float2(acc[mt][nt][2] + bb.x, acc[mt][nt][3] + bb.y);
        }
    }
}

// ---------------------------------------------------------------------------
// Pipelined attention. 512 threads.
// S-side (warps 0-7): stage K-frags, S=QK^T, softmax, publish P+alpha (tile t)
// O-side (warps 8-15): stage V/K-frags, O_v += P V, O_k += P K (tile t-1)
// Fragment-major B layouts: one LDS.64 per B-fragment, XOR-swizzled.
// ---------------------------------------------------------------------------
#define SPP 68

#define KFS_OFF 0                    // 4096  : S-phase K frags (single buf)
#define VF_OFF  4096                 // 8192  : V frags (2 bufs x 4096)
#define KTF_OFF 12288                // 8192  : O-phase K frags (2 bufs)
#define QS_OFF  20480                // 8704  : Q staged (row-major)
#define PP_OFF  29184                // 17408 : P (2 bufs x 8704)
#define PP_SZ   8704
#define AL_OFF  46592                // 256   : alphas (2 bufs x 128)
#define LI_OFF  46848                // 128   : 1/l
#define SM_WORDS 46976

__global__ __launch_bounds__(512, 1) void attn_kernel(
    const int* __restrict__ mask, float* __restrict__ out_k, float* __restrict__ out_v)
{
    extern __shared__ unsigned sm[];
    unsigned* KFS = sm + KFS_OFF;
    unsigned* Qs  = sm + QS_OFF;
    float* alphas = (float*)(sm + AL_OFF);
    float* linv   = (float*)(sm + LI_OFF);

    const int tid  = threadIdx.x;
    const int warp = tid >> 5, lane = tid & 31;
    const int g = lane >> 2, tg = lane & 3;
    const int side = warp >> 3;          // 0: S-side   1: O-side
    const int wr   = warp & 7;
    const int w16  = wr * 16;
    const int q0 = blockIdx.x * 128;
    const int by = blockIdx.y;
    const int b  = by >> 4;
    const int h  = by & 15;

    const float* Qg = g_Qh + ((size_t)by * LQ + q0) * DH;
    const float* Kg = g_Kh + (size_t)by * LK * DH;
    const float* Vg = g_Vh + (size_t)by * LK * DH;

    // ---- stage Q (all 512 threads, once) ----
#pragma unroll
    for (int rep = 0; rep < 4; rep++) {
        int idx = tid + 512 * rep;
        int r = idx >> 4, d4 = idx & 15;
        float4 qv = *(const float4*)(Qg + (size_t)r * DH + d4 * 4);
        *(uint4*)&Qs[r * SPP + d4 * 4] = make_uint4(
            f2tf(qv.x * 0.125f), f2tf(qv.y * 0.125f),
            f2tf(qv.z * 0.125f), f2tf(qv.w * 0.125f));
    }

    // acc[0..7]: S-side scratch s / O-side O_v ; acc[8..15]: O-side O_k
    float acc[16][4];
#pragma unroll
    for (int nt = 0; nt < 16; nt++)
#pragma unroll
        for (int i = 0; i < 4; i++) acc[nt][i] = 0.f;
    float mi0 = -1e30f, mi1 = -1e30f, li0 = 0.f, li1 = 0.f;

    for (int t = 0; t <= NT; t++) {
        __syncthreads();   // publishes P[t-1]/alpha[t-1]; closes all prior-buf reads

        if (side == 0) {
            if (t < NT) {
                const int k0 = t * 64;
                // ---- stage K S-frags (256 threads, private to S-side) ----
#pragma unroll
                for (int rep = 0; rep < 4; rep++) {
                    int idx2 = tid + 256 * rep;
                    int key = idx2 >> 4, c4 = idx2 & 15;
                    float4 kv = *(const float4*)(Kg + (size_t)(k0 + key) * DH + c4 * 4);
                    int nt_ = key >> 3, gr = key & 7;
                    int kb = c4 >> 1, slot = c4 & 1;
                    unsigned vals[4] = {f2tf(kv.x), f2tf(kv.y), f2tf(kv.z), f2tf(kv.w)};
#pragma unroll
                    for (int j = 0; j < 4; j++) {
                        int rl = gr * 4 + j;
                        int chunk = (kb * 8 + nt_) * 32 + (rl ^ (((kb ^ nt_) & 15) << 1));
                        KFS[chunk * 2 + slot] = vals[j];
                    }
                }
                asm volatile("bar.sync 1, 256;" ::: "memory");

                // ---- S = Q K^T ----
#pragma unroll
                for (int nt = 0; nt < 8; nt++)
#pragma unroll
                    for (int i = 0; i < 4; i++) acc[nt][i] = 0.f;
#pragma unroll
                for (int kb = 0; kb < 8; kb++) {
                    unsigned qa[4];
                    int qb = (w16 + g) * SPP + kb * 8 + tg;
                    qa[0] = Qs[qb];
                    qa[1] = Qs[qb + 8 * SPP];
                    qa[2] = Qs[qb + 4];
                    qa[3] = Qs[qb + 8 * SPP + 4];
#pragma unroll
                    for (int nt = 0; nt < 8; nt++) {
                        int chunk = (kb * 8 + nt) * 32 + (lane ^ (((kb ^ nt) & 15) << 1));
                        uint2 bf = *(uint2*)&KFS[chunk * 2];
                        unsigned bfr[2] = {bf.x, bf.y};
                        mma_tf32(acc[nt], qa, bfr);
                    }
                }

                // ---- mask + online softmax ----
                const int qr0 = q0 + w16 + g;
                const size_t mrow0 = ((size_t)b * LQ + qr0) * LK + k0;
                const size_t mrow1 = mrow0 + 8 * (size_t)LK;
#pragma unroll
                for (int nt = 0; nt < 8; nt++) {
                    int col = nt * 8 + 2 * tg;
                    int2 m0v = *(const int2*)(mask + mrow0 + col);
                    int2 m1v = *(const int2*)(mask + mrow1 + col);
                    if (m0v.x == 0) acc[nt][0] = -1e30f;
                    if (m0v.y == 0) acc[nt][1] = -1e30f;
                    if (m1v.x == 0) acc[nt][2] = -1e30f;
                    if (m1v.y == 0) acc[nt][3] = -1e30f;
                }
                float mx0 = -1e30f, mx1 = -1e30f;
#pragma unroll
                for (int nt = 0; nt < 8; nt++) {
                    mx0 = fmaxf(mx0, fmaxf(acc[nt][0], acc[nt][1]));
                    mx1 = fmaxf(mx1, fmaxf(acc[nt][2], acc[nt][3]));
                }
                mx0 = fmaxf(mx0, __shfl_xor_sync(0xffffffffu, mx0, 1));
                mx0 = fmaxf(mx0, __shfl_xor_sync(0xffffffffu, mx0, 2));
                mx1 = fmaxf(mx1, __shfl_xor_sync(0xffffffffu, mx1, 1));
                mx1 = fmaxf(mx1, __shfl_xor_sync(0xffffffffu, mx1, 2));
                float mn0 = fmaxf(mi0, mx0), mn1 = fmaxf(mi1, mx1);
                float al0 = __expf(mi0 - mn0), al1 = __expf(mi1 - mn1);
                float rs0 = 0.f, rs1 = 0.f;
#pragma unroll
                for (int nt = 0; nt < 8; nt++) {
                    acc[nt][0] = __expf(acc[nt][0] - mn0); rs0 += acc[nt][0];
                    acc[nt][1] = __expf(acc[nt][1] - mn0); rs0 += acc[nt][1];
                    acc[nt][2] = __expf(acc[nt][2] - mn1); rs1 += acc[nt][2];
                    acc[nt][3] = __expf(acc[nt][3] - mn1); rs1 += acc[nt][3];
                }
                rs0 += __shfl_xor_sync(0xffffffffu, rs0, 1);
                rs0 += __shfl_xor_sync(0xffffffffu, rs0, 2);
                rs1 += __shfl_xor_sync(0xffffffffu, rs1, 1);
                rs1 += __shfl_xor_sync(0xffffffffu, rs1, 2);
                li0 = li0 * al0 + rs0; li1 = li1 * al1 + rs1;
                mi0 = mn0; mi1 = mn1;

                unsigned* Pb = sm + PP_OFF + (t & 1) * PP_SZ;
#pragma unroll
                for (int nt = 0; nt < 8; nt++) {
                    int base = (w16 + g) * SPP + nt * 8 + 2 * tg;
                    Pb[base]               = f2tf(acc[nt][0]);
                    Pb[base + 1]           = f2tf(acc[nt][1]);
                    Pb[base + 8 * SPP]     = f2tf(acc[nt][2]);
                    Pb[base + 8 * SPP + 1] = f2tf(acc[nt][3]);
                }
                if (tg == 0) {
                    alphas[(t & 1) * 128 + w16 + g]     = al0;
                    alphas[(t & 1) * 128 + w16 + 8 + g] = al1;
                }
            }
        } else {
            if (t < NT) {
                const int k0 = t * 64;
                unsigned* VFb  = sm + VF_OFF  + (t & 1) * 4096;
                unsigned* KTFb = sm + KTF_OFF + (t & 1) * 4096;
                const int ot = tid - 256;
#pragma unroll
                for (int rep = 0; rep < 4; rep++) {
                    int idx2 = ot + 256 * rep;
                    int key = idx2 >> 4, c4 = idx2 & 15;
                    float4 vv = *(const float4*)(Vg + (size_t)(k0 + key) * DH + c4 * 4);
                    float4 kv = *(const float4*)(Kg + (size_t)(k0 + key) * DH + c4 * 4);
                    int kbv = key >> 3, slot = (key & 7) >> 2, tgr = key & 3;
                    int nt_ = c4 >> 1;
                    unsigned va[4] = {f2tf(vv.x), f2tf(vv.y), f2tf(vv.z), f2tf(vv.w)};
                    unsigned ka[4] = {f2tf(kv.x), f2tf(kv.y), f2tf(kv.z), f2tf(kv.w)};
#pragma unroll
                    for (int j = 0; j < 4; j++) {
                        int gr = (c4 & 1) * 4 + j;
                        int rl = gr * 4 + tgr;
                        int chunk = (kbv * 8 + nt_) * 32 + (rl ^ (((kbv ^ nt_) & 15) << 1));
                        VFb[chunk * 2 + slot]  = va[j];
                        KTFb[chunk * 2 + slot] = ka[j];
                    }
                }
            }
            if (t > 0) {
                const int pb = (t - 1) & 1;
                unsigned* Pb   = sm + PP_OFF + pb * PP_SZ;
                unsigned* VFb  = sm + VF_OFF  + pb * 4096;
                unsigned* KTFb = sm + KTF_OFF + pb * 4096;
                float a0 = alphas[pb * 128 + w16 + g];
                float a1 = alphas[pb * 128 + w16 + 8 + g];
#pragma unroll
                for (int nt = 0; nt < 16; nt++) {
                    acc[nt][0] *= a0; acc[nt][1] *= a0;
                    acc[nt][2] *= a1; acc[nt][3] *= a1;
                }
#pragma unroll
                for (int kb = 0; kb < 8; kb++) {
                    unsigned pa[4];
                    int base = (w16 + g) * SPP + kb * 8 + tg;
                    pa[0] = Pb[base];
                    pa[1] = Pb[base + 8 * SPP];
                    pa[2] = Pb[base + 4];
                    pa[3] = Pb[base + 8 * SPP + 4];
#pragma unroll
                    for (int nt = 0; nt < 8; nt++) {
                        int chunk = (kb * 8 + nt) * 32 + (lane ^ (((kb ^ nt) & 15) << 1));
                        uint2 vf = *(uint2*)&VFb[chunk * 2];
                        unsigned vb[2] = {vf.x, vf.y};
                        mma_tf32(acc[nt], pa, vb);
                        uint2 kf = *(uint2*)&KTFb[chunk * 2];
                        unsigned kb2[2] = {kf.x, kf.y};
                        mma_tf32(acc[8 + nt], pa, kb2);
                    }
                }
            }
        }
    }

    // ---- epilogue ----
    if (side == 0) {
        if (tg == 0) {
            linv[w16 + g]     = 1.f / li0;
            linv[w16 + 8 + g] = 1.f / li1;
        }
    }
    __syncthreads();
    if (side == 1) {
        float inv0 = linv[w16 + g];
        float inv1 = linv[w16 + 8 + g];
        int r0 = q0 + w16 + g;
#pragma unroll
        for (int nt = 0; nt < 8; nt++) {
            int d = nt * 8 + 2 * tg;
            size_t o0 = ((size_t)b * LQ + r0) * DM + h * DH + d;
            size_t o1 = ((size_t)b * LQ + r0 + 8) * DM + h * DH + d;
            *(float2*)(out_v + o0) = make_float2(acc[nt][0] * inv0, acc[nt][1] * inv0);
            *(float2*)(out_v + o1) = make_float2(acc[nt][2] * inv1, acc[nt][3] * inv1);
            *(float2*)(out_k + o0) = make_float2(acc[8 + nt][0] * inv0, acc[8 + nt][1] * inv0);
            *(float2*)(out_k + o1) = make_float2(acc[8 + nt][2] * inv1, acc[8 + nt][3] * inv1);
        }
    }
}

// ---------------------------------------------------------------------------
extern "C" void kernel_launch(void* const* d_in, const int* in_sizes, int n_in,
                              void* d_out, int out_size)
{
    const float* q    = (const float*)d_in[0];
    const float* k    = (const float*)d_in[1];
    const float* v    = (const float*)d_in[2];
    const int*   mask = (const int*)  d_in[3];
    const float* Wq   = (const float*)d_in[4];
    const float* bq   = (const float*)d_in[5];
    const float* Wk   = (const float*)d_in[6];
    const float* bk   = (const float*)d_in[7];
    const float* Wv   = (const float*)d_in[8];
    const float* bv   = (const float*)d_in[9];

    float* out_k = (float*)d_out;
    float* out_v = (float*)d_out + (size_t)BB * LQ * DM;

    static int smem_set = 0;
    if (!smem_set) {
        cudaFuncSetAttribute(attn_kernel, cudaFuncAttributeMaxDynamicSharedMemorySize,
                             SM_WORDS * (int)sizeof(unsigned));
        smem_set = 1;
    }

    dim3 pgrid(DM / 128, MTOT / 128, 3);
    proj_kernel<<<pgrid, 256>>>(q, k, v, Wq, bq, Wk, bk, Wv, bv);

    dim3 agrid(LQ / 128, BB * NH);
    attn_kernel<<<agrid, 512, SM_WORDS * (int)sizeof(unsigned)>>>(mask, out_k, out_v);
}

// round 13
// speedup vs baseline: 3.2523x; 1.0821x over previous
#include <cuda_runtime.h>
#include <math.h>

#define NH   16
#define DH   64
#define DM   1024
#define BB   2
#define LQ   2048
#define LK   2048
#define MTOT (BB*LQ)
#define NT   (LK/64)

// Head-major projected scratch: [(b*NH+h), L, DH]
__device__ float g_Qh[BB*NH*LQ*DH];
__device__ float g_Kh[BB*NH*LK*DH];
__device__ float g_Vh[BB*NH*LK*DH];

__device__ __forceinline__ unsigned f2tf(float f) {
    unsigned r;
    asm("cvt.rna.tf32.f32 %0, %1;" : "=r"(r) : "f"(f));
    return r;
}

__device__ __forceinline__ void mma_tf32(float* d, const unsigned* a, const unsigned* b) {
    asm volatile(
        "mma.sync.aligned.m16n8k8.row.col.f32.tf32.tf32.f32 "
        "{%0,%1,%2,%3}, {%4,%5,%6,%7}, {%8,%9}, {%0,%1,%2,%3};"
        : "+f"(d[0]), "+f"(d[1]), "+f"(d[2]), "+f"(d[3])
        : "r"(a[0]), "r"(a[1]), "r"(a[2]), "r"(a[3]), "r"(b[0]), "r"(b[1]));
}

// ---------------------------------------------------------------------------
// Projection: double-buffered tf32 warp-mma, head-major out.
// BM=BN=128, BK=32, 256 threads. Prefetch next slab in regs during compute.
// ---------------------------------------------------------------------------
#define PST 36
#define PBUF (128 * PST)            // words per array per buffer (4608)
#define PROJ_SM_WORDS (PBUF * 4)    // As0,Ws0,As1,Ws1

__global__ __launch_bounds__(256) void proj_kernel(
    const float* __restrict__ q, const float* __restrict__ k, const float* __restrict__ v,
    const float* __restrict__ Wq, const float* __restrict__ bq,
    const float* __restrict__ Wk, const float* __restrict__ bk,
    const float* __restrict__ Wv, const float* __restrict__ bv)
{
    const float *A, *W, *bias;
    float* out;
    if (blockIdx.z == 0)      { A = q; W = Wq; bias = bq; out = g_Qh; }
    else if (blockIdx.z == 1) { A = k; W = Wk; bias = bk; out = g_Kh; }
    else                      { A = v; W = Wv; bias = bv; out = g_Vh; }

    extern __shared__ unsigned psm[];

    const int tid  = threadIdx.x;
    const int warp = tid >> 5, lane = tid & 31;
    const int g = lane >> 2, tg = lane & 3;
    const int wm = warp >> 2;
    const int wn = warp & 3;
    const int m0 = blockIdx.y * 128;
    const int n0 = blockIdx.x * 128;

    float acc[4][4][4];
#pragma unroll
    for (int mt = 0; mt < 4; mt++)
#pragma unroll
        for (int nt = 0; nt < 4; nt++)
#pragma unroll
            for (int i = 0; i < 4; i++) acc[mt][nt][i] = 0.f;

    const int lrow = tid >> 3;      // 0..31
    const int lc4  = tid & 7;

    // ---- prologue: load slab 0 directly to buffer 0 ----
    {
        unsigned* As = psm;
        unsigned* Ws = psm + PBUF;
#pragma unroll
        for (int rep = 0; rep < 4; rep++) {
            int row = lrow + rep * 32;
            float4 av = *(const float4*)(A + (size_t)(m0 + row) * DM + lc4 * 4);
            *(uint4*)&As[row * PST + lc4 * 4] =
                make_uint4(f2tf(av.x), f2tf(av.y), f2tf(av.z), f2tf(av.w));
            float4 wv = *(const float4*)(W + (size_t)(n0 + row) * DM + lc4 * 4);
            *(uint4*)&Ws[row * PST + lc4 * 4] =
                make_uint4(f2tf(wv.x), f2tf(wv.y), f2tf(wv.z), f2tf(wv.w));
        }
    }
    __syncthreads();

    for (int ks = 0; ks < DM / 32; ks++) {
        unsigned* As = psm + (ks & 1) * (2 * PBUF);
        unsigned* Ws = As + PBUF;

        // prefetch next slab into registers (overlaps with MMAs below)
        float4 pav[4], pwv[4];
        if (ks + 1 < DM / 32) {
            int kn = (ks + 1) * 32;
#pragma unroll
            for (int rep = 0; rep < 4; rep++) {
                int row = lrow + rep * 32;
                pav[rep] = *(const float4*)(A + (size_t)(m0 + row) * DM + kn + lc4 * 4);
                pwv[rep] = *(const float4*)(W + (size_t)(n0 + row) * DM + kn + lc4 * 4);
            }
        }

#pragma unroll
        for (int kk = 0; kk < 4; kk++) {
            unsigned a[4][4], b[4][2];
#pragma unroll
            for (int mt = 0; mt < 4; mt++) {
                int base = (wm * 64 + mt * 16 + g) * PST + kk * 8 + tg;
                a[mt][0] = As[base];
                a[mt][1] = As[base + 8 * PST];
                a[mt][2] = As[base + 4];
                a[mt][3] = As[base + 8 * PST + 4];
            }
#pragma unroll
            for (int nt = 0; nt < 4; nt++) {
                int base = (wn * 32 + nt * 8 + g) * PST + kk * 8 + tg;
                b[nt][0] = Ws[base];
                b[nt][1] = Ws[base + 4];
            }
#pragma unroll
            for (int mt = 0; mt < 4; mt++)
#pragma unroll
                for (int nt = 0; nt < 4; nt++)
                    mma_tf32(acc[mt][nt], a[mt], b[nt]);
        }

        // store prefetched slab into the other buffer
        if (ks + 1 < DM / 32) {
            unsigned* Asn = psm + ((ks + 1) & 1) * (2 * PBUF);
            unsigned* Wsn = Asn + PBUF;
#pragma unroll
            for (int rep = 0; rep < 4; rep++) {
                int row = lrow + rep * 32;
                *(uint4*)&Asn[row * PST + lc4 * 4] = make_uint4(
                    f2tf(pav[rep].x), f2tf(pav[rep].y), f2tf(pav[rep].z), f2tf(pav[rep].w));
                *(uint4*)&Wsn[row * PST + lc4 * 4] = make_uint4(
                    f2tf(pwv[rep].x), f2tf(pwv[rep].y), f2tf(pwv[rep].z), f2tf(pwv[rep].w));
            }
        }
        __syncthreads();
    }

#pragma unroll
    for (int nt = 0; nt < 4; nt++) {
        int n = n0 + wn * 32 + nt * 8 + 2 * tg;
        int h = n >> 6, d = n & 63;
        float2 bb = *(const float2*)(bias + n);
#pragma unroll
        for (int mt = 0; mt < 4; mt++) {
            int m = m0 + wm * 64 + mt * 16 + g;
            int b_ = m >> 11, r = m & (LQ - 1);
            float* p0 = out + (((size_t)b_ * NH + h) * LQ + r) * DH + d;
            *(float2*)p0 = make_float2(acc[mt][nt][0] + bb.x, acc[mt][nt][1] + bb.y);
            float* p1 = out + (((size_t)b_ * NH + h) * LQ + (r + 8)) * DH + d;
            *(float2*)p1 = make_float2(acc[mt][nt][2] + bb.x, acc[mt][nt][3] + bb.y);
        }
    }
}

// ---------------------------------------------------------------------------
// Pipelined attention. 512 threads.
// S-side (warps 0-7): stage K-frags, S=QK^T, softmax, publish P+alpha (tile t)
// O-side (warps 8-11: O_v rows o*32..+31; warps 12-15: O_k): tile t-1,
//   B-fragments shared across two row-tiles (one LDS.64 feeds two MMAs).
// ---------------------------------------------------------------------------
#define SPP 68

#define KFS_OFF 0                    // 4096  : S-phase K frags (single buf)
#define VF_OFF  4096                 // 8192  : V frags (2 bufs x 4096)
#define KTF_OFF 12288                // 8192  : O-phase K frags (2 bufs)
#define QS_OFF  20480                // 8704  : Q staged (row-major)
#define PP_OFF  29184                // 17408 : P (2 bufs x 8704)
#define PP_SZ   8704
#define AL_OFF  46592                // 256   : alphas (2 bufs x 128)
#define LI_OFF  46848                // 128   : 1/l
#define SM_WORDS 46976

__global__ __launch_bounds__(512, 1) void attn_kernel(
    const int* __restrict__ mask, float* __restrict__ out_k, float* __restrict__ out_v)
{
    extern __shared__ unsigned sm[];
    unsigned* KFS = sm + KFS_OFF;
    unsigned* Qs  = sm + QS_OFF;
    float* alphas = (float*)(sm + AL_OFF);
    float* linv   = (float*)(sm + LI_OFF);

    const int tid  = threadIdx.x;
    const int warp = tid >> 5, lane = tid & 31;
    const int g = lane >> 2, tg = lane & 3;
    const int side = warp >> 3;          // 0: S-side   1: O-side
    const int wr   = warp & 7;
    const int w16  = wr * 16;
    const int q0 = blockIdx.x * 128;
    const int by = blockIdx.y;
    const int b  = by >> 4;
    const int h  = by & 15;

    // O-side role: warps 8-11 -> O_v, 12-15 -> O_k; 32 rows each
    const int oidx = warp - 8;           // 0..7 (valid when side==1)
    const int osel = oidx >> 2;          // 0: O_v, 1: O_k
    const int rg   = (oidx & 3) * 32;    // row base

    const float* Qg = g_Qh + ((size_t)by * LQ + q0) * DH;
    const float* Kg = g_Kh + (size_t)by * LK * DH;
    const float* Vg = g_Vh + (size_t)by * LK * DH;

    // ---- stage Q (all 512 threads, once) ----
#pragma unroll
    for (int rep = 0; rep < 4; rep++) {
        int idx = tid + 512 * rep;
        int r = idx >> 4, d4 = idx & 15;
        float4 qv = *(const float4*)(Qg + (size_t)r * DH + d4 * 4);
        *(uint4*)&Qs[r * SPP + d4 * 4] = make_uint4(
            f2tf(qv.x * 0.125f), f2tf(qv.y * 0.125f),
            f2tf(qv.z * 0.125f), f2tf(qv.w * 0.125f));
    }

    // acc[0..7]: S scratch s / O rows rg..rg+15 ; acc[8..15]: O rows rg+16..rg+31
    float acc[16][4];
#pragma unroll
    for (int nt = 0; nt < 16; nt++)
#pragma unroll
        for (int i = 0; i < 4; i++) acc[nt][i] = 0.f;
    float mi0 = -1e30f, mi1 = -1e30f, li0 = 0.f, li1 = 0.f;

    for (int t = 0; t <= NT; t++) {
        __syncthreads();   // publishes P[t-1]/alpha[t-1]; closes all prior-buf reads

        if (side == 0) {
            if (t < NT) {
                const int k0 = t * 64;
                // ---- stage K S-frags (256 threads, private to S-side) ----
#pragma unroll
                for (int rep = 0; rep < 4; rep++) {
                    int idx2 = tid + 256 * rep;
                    int key = idx2 >> 4, c4 = idx2 & 15;
                    float4 kv = *(const float4*)(Kg + (size_t)(k0 + key) * DH + c4 * 4);
                    int nt_ = key >> 3, gr = key & 7;
                    int kb = c4 >> 1, slot = c4 & 1;
                    unsigned vals[4] = {f2tf(kv.x), f2tf(kv.y), f2tf(kv.z), f2tf(kv.w)};
#pragma unroll
                    for (int j = 0; j < 4; j++) {
                        int rl = gr * 4 + j;
                        int chunk = (kb * 8 + nt_) * 32 + (rl ^ (((kb ^ nt_) & 15) << 1));
                        KFS[chunk * 2 + slot] = vals[j];
                    }
                }
                asm volatile("bar.sync 1, 256;" ::: "memory");

                // ---- S = Q K^T ----
#pragma unroll
                for (int nt = 0; nt < 8; nt++)
#pragma unroll
                    for (int i = 0; i < 4; i++) acc[nt][i] = 0.f;
#pragma unroll
                for (int kb = 0; kb < 8; kb++) {
                    unsigned qa[4];
                    int qb = (w16 + g) * SPP + kb * 8 + tg;
                    qa[0] = Qs[qb];
                    qa[1] = Qs[qb + 8 * SPP];
                    qa[2] = Qs[qb + 4];
                    qa[3] = Qs[qb + 8 * SPP + 4];
#pragma unroll
                    for (int nt = 0; nt < 8; nt++) {
                        int chunk = (kb * 8 + nt) * 32 + (lane ^ (((kb ^ nt) & 15) << 1));
                        uint2 bf = *(uint2*)&KFS[chunk * 2];
                        unsigned bfr[2] = {bf.x, bf.y};
                        mma_tf32(acc[nt], qa, bfr);
                    }
                }

                // ---- mask + online softmax ----
                const int qr0 = q0 + w16 + g;
                const size_t mrow0 = ((size_t)b * LQ + qr0) * LK + k0;
                const size_t mrow1 = mrow0 + 8 * (size_t)LK;
#pragma unroll
                for (int nt = 0; nt < 8; nt++) {
                    int col = nt * 8 + 2 * tg;
                    int2 m0v = *(const int2*)(mask + mrow0 + col);
                    int2 m1v = *(const int2*)(mask + mrow1 + col);
                    if (m0v.x == 0) acc[nt][0] = -1e30f;
                    if (m0v.y == 0) acc[nt][1] = -1e30f;
                    if (m1v.x == 0) acc[nt][2] = -1e30f;
                    if (m1v.y == 0) acc[nt][3] = -1e30f;
                }
                float mx0 = -1e30f, mx1 = -1e30f;
#pragma unroll
                for (int nt = 0; nt < 8; nt++) {
                    mx0 = fmaxf(mx0, fmaxf(acc[nt][0], acc[nt][1]));
                    mx1 = fmaxf(mx1, fmaxf(acc[nt][2], acc[nt][3]));
                }
                mx0 = fmaxf(mx0, __shfl_xor_sync(0xffffffffu, mx0, 1));
                mx0 = fmaxf(mx0, __shfl_xor_sync(0xffffffffu, mx0, 2));
                mx1 = fmaxf(mx1, __shfl_xor_sync(0xffffffffu, mx1, 1));
                mx1 = fmaxf(mx1, __shfl_xor_sync(0xffffffffu, mx1, 2));
                float mn0 = fmaxf(mi0, mx0), mn1 = fmaxf(mi1, mx1);
                float al0 = __expf(mi0 - mn0), al1 = __expf(mi1 - mn1);
                float rs0 = 0.f, rs1 = 0.f;
#pragma unroll
                for (int nt = 0; nt < 8; nt++) {
                    acc[nt][0] = __expf(acc[nt][0] - mn0); rs0 += acc[nt][0];
                    acc[nt][1] = __expf(acc[nt][1] - mn0); rs0 += acc[nt][1];
                    acc[nt][2] = __expf(acc[nt][2] - mn1); rs1 += acc[nt][2];
                    acc[nt][3] = __expf(acc[nt][3] - mn1); rs1 += acc[nt][3];
                }
                rs0 += __shfl_xor_sync(0xffffffffu, rs0, 1);
                rs0 += __shfl_xor_sync(0xffffffffu, rs0, 2);
                rs1 += __shfl_xor_sync(0xffffffffu, rs1, 1);
                rs1 += __shfl_xor_sync(0xffffffffu, rs1, 2);
                li0 = li0 * al0 + rs0; li1 = li1 * al1 + rs1;
                mi0 = mn0; mi1 = mn1;

                unsigned* Pb = sm + PP_OFF + (t & 1) * PP_SZ;
#pragma unroll
                for (int nt = 0; nt < 8; nt++) {
                    int base = (w16 + g) * SPP + nt * 8 + 2 * tg;
                    Pb[base]               = f2tf(acc[nt][0]);
                    Pb[base + 1]           = f2tf(acc[nt][1]);
                    Pb[base + 8 * SPP]     = f2tf(acc[nt][2]);
                    Pb[base + 8 * SPP + 1] = f2tf(acc[nt][3]);
                }
                if (tg == 0) {
                    alphas[(t & 1) * 128 + w16 + g]     = al0;
                    alphas[(t & 1) * 128 + w16 + 8 + g] = al1;
                }
            }
        } else {
            if (t < NT) {
                const int k0 = t * 64;
                unsigned* VFb  = sm + VF_OFF  + (t & 1) * 4096;
                unsigned* KTFb = sm + KTF_OFF + (t & 1) * 4096;
                const int ot = tid - 256;
#pragma unroll
                for (int rep = 0; rep < 4; rep++) {
                    int idx2 = ot + 256 * rep;
                    int key = idx2 >> 4, c4 = idx2 & 15;
                    float4 vv = *(const float4*)(Vg + (size_t)(k0 + key) * DH + c4 * 4);
                    float4 kv = *(const float4*)(Kg + (size_t)(k0 + key) * DH + c4 * 4);
                    int kbv = key >> 3, slot = (key & 7) >> 2, tgr = key & 3;
                    int nt_ = c4 >> 1;
                    unsigned va[4] = {f2tf(vv.x), f2tf(vv.y), f2tf(vv.z), f2tf(vv.w)};
                    unsigned ka[4] = {f2tf(kv.x), f2tf(kv.y), f2tf(kv.z), f2tf(kv.w)};
#pragma unroll
                    for (int j = 0; j < 4; j++) {
                        int gr = (c4 & 1) * 4 + j;
                        int rl = gr * 4 + tgr;
                        int chunk = (kbv * 8 + nt_) * 32 + (rl ^ (((kbv ^ nt_) & 15) << 1));
                        VFb[chunk * 2 + slot]  = va[j];
                        KTFb[chunk * 2 + slot] = ka[j];
                    }
                }
            }
            if (t > 0) {
                const int pb = (t - 1) & 1;
                unsigned* Pb = sm + PP_OFF + pb * PP_SZ;
                unsigned* Bf = sm + (osel ? KTF_OFF : VF_OFF) + pb * 4096;
                float a0 = alphas[pb * 128 + rg + g];
                float a1 = alphas[pb * 128 + rg + 8 + g];
                float a2 = alphas[pb * 128 + rg + 16 + g];
                float a3 = alphas[pb * 128 + rg + 24 + g];
#pragma unroll
                for (int nt = 0; nt < 8; nt++) {
                    acc[nt][0] *= a0;     acc[nt][1] *= a0;
                    acc[nt][2] *= a1;     acc[nt][3] *= a1;
                    acc[8 + nt][0] *= a2; acc[8 + nt][1] *= a2;
                    acc[8 + nt][2] *= a3; acc[8 + nt][3] *= a3;
                }
#pragma unroll
                for (int kb = 0; kb < 8; kb++) {
                    unsigned paA[4], paB[4];
                    int baseA = (rg + g) * SPP + kb * 8 + tg;
                    paA[0] = Pb[baseA];
                    paA[1] = Pb[baseA + 8 * SPP];
                    paA[2] = Pb[baseA + 4];
                    paA[3] = Pb[baseA + 8 * SPP + 4];
                    int baseB = (rg + 16 + g) * SPP + kb * 8 + tg;
                    paB[0] = Pb[baseB];
                    paB[1] = Pb[baseB + 8 * SPP];
                    paB[2] = Pb[baseB + 4];
                    paB[3] = Pb[baseB + 8 * SPP + 4];
#pragma unroll
                    for (int nt = 0; nt < 8; nt++) {
                        int chunk = (kb * 8 + nt) * 32 + (lane ^ (((kb ^ nt) & 15) << 1));
                        uint2 bf = *(uint2*)&Bf[chunk * 2];
                        unsigned bfr[2] = {bf.x, bf.y};
                        mma_tf32(acc[nt], paA, bfr);
                        mma_tf32(acc[8 + nt], paB, bfr);
                    }
                }
            }
        }
    }

    // ---- epilogue ----
    if (side == 0) {
        if (tg == 0) {
            linv[w16 + g]     = 1.f / li0;
            linv[w16 + 8 + g] = 1.f / li1;
        }
    }
    __syncthreads();
    if (side == 1) {
        float inv0 = linv[rg + g];
        float inv1 = linv[rg + 8 + g];
        float inv2 = linv[rg + 16 + g];
        float inv3 = linv[rg + 24 + g];
        float* outp = osel ? out_k : out_v;
        int r0 = q0 + rg + g;
#pragma unroll
        for (int nt = 0; nt < 8; nt++) {
            int d = nt * 8 + 2 * tg;
            size_t o0 = ((size_t)b * LQ + r0) * DM + h * DH + d;
            size_t o1 = ((size_t)b * LQ + r0 + 8) * DM + h * DH + d;
            size_t o2 = ((size_t)b * LQ + r0 + 16) * DM + h * DH + d;
            size_t o3 = ((size_t)b * LQ + r0 + 24) * DM + h * DH + d;
            *(float2*)(outp + o0) = make_float2(acc[nt][0] * inv0, acc[nt][1] * inv0);
            *(float2*)(outp + o1) = make_float2(acc[nt][2] * inv1, acc[nt][3] * inv1);
            *(float2*)(outp + o2) = make_float2(acc[8 + nt][0] * inv2, acc[8 + nt][1] * inv2);
            *(float2*)(outp + o3) = make_float2(acc[8 + nt][2] * inv3, acc[8 + nt][3] * inv3);
        }
    }
}

// ---------------------------------------------------------------------------
extern "C" void kernel_launch(void* const* d_in, const int* in_sizes, int n_in,
                              void* d_out, int out_size)
{
    const float* q    = (const float*)d_in[0];
    const float* k    = (const float*)d_in[1];
    const float* v    = (const float*)d_in[2];
    const int*   mask = (const int*)  d_in[3];
    const float* Wq   = (const float*)d_in[4];
    const float* bq   = (const float*)d_in[5];
    const float* Wk   = (const float*)d_in[6];
    const float* bk   = (const float*)d_in[7];
    const float* Wv   = (const float*)d_in[8];
    const float* bv   = (const float*)d_in[9];

    float* out_k = (float*)d_out;
    float* out_v = (float*)d_out + (size_t)BB * LQ * DM;

    static int smem_set = 0;
    if (!smem_set) {
        cudaFuncSetAttribute(attn_kernel, cudaFuncAttributeMaxDynamicSharedMemorySize,
                             SM_WORDS * (int)sizeof(unsigned));
        cudaFuncSetAttribute(proj_kernel, cudaFuncAttributeMaxDynamicSharedMemorySize,
                             PROJ_SM_WORDS * (int)sizeof(unsigned));
        smem_set = 1;
    }

    dim3 pgrid(DM / 128, MTOT / 128, 3);
    proj_kernel<<<pgrid, 256, PROJ_SM_WORDS * (int)sizeof(unsigned)>>>(
        q, k, v, Wq, bq, Wk, bk, Wv, bv);

    dim3 agrid(LQ / 128, BB * NH);
    attn_kernel<<<agrid, 512, SM_WORDS * (int)sizeof(unsigned)>>>(mask, out_k, out_v);
}